// round 9
// baseline (speedup 1.0000x reference)
#include <cuda_runtime.h>
#include <cuda_bf16.h>

// SparseLinear: out[b,k] = dot(embed[b,:], weight[shortlist[b,k],:]) + bias[shortlist[b,k]]
// B=256, K=500, D=512, L=262144
// NOTE: reference declares shortlist int64, but JAX default (x64 disabled)
// downcasts to int32 — the device buffer is int32. Round 7's long long read
// fused adjacent indices -> OOB gather -> illegal memory access.
//
// HBM-bound gather: ~230MB effective weight-row traffic dominates. Strategy:
//   - block caches embed[b] in smem (read once per block instead of per (b,k))
//   - one warp per (b,k): 32 lanes x 4 float4 = 2KB row, coalesced, MLP=4/lane
//   - warp shfl reduction, lane0 adds bias, stores.

#define B_DIM 256
#define K_DIM 500
#define D_DIM 512
#define SPLITS 4
#define K_PER_BLOCK ((K_DIM + SPLITS - 1) / SPLITS)   // 125
#define THREADS 256
#define WARPS (THREADS / 32)

__global__ __launch_bounds__(THREADS)
void sparse_linear_kernel(const float* __restrict__ embed,
                          const int* __restrict__ shortlist,
                          const float* __restrict__ weight,
                          const float* __restrict__ bias,
                          float* __restrict__ out)
{
    __shared__ float4 s_embed[D_DIM / 4];   // 128 float4 = 2KB

    const int b    = blockIdx.x;
    const int tid  = threadIdx.x;
    const int warp = tid >> 5;
    const int lane = tid & 31;

    // Cooperative load of embed[b] into smem as float4 (threads 0..127 do one each)
    const float4* embed_row = reinterpret_cast<const float4*>(embed + (size_t)b * D_DIM);
    if (tid < D_DIM / 4) {
        s_embed[tid] = embed_row[tid];
    }
    __syncthreads();

    const int k_begin = blockIdx.y * K_PER_BLOCK;
    int k_end = k_begin + K_PER_BLOCK;
    if (k_end > K_DIM) k_end = K_DIM;

    const int* sl_row = shortlist + (size_t)b * K_DIM;

    for (int k = k_begin + warp; k < k_end; k += WARPS) {
        const int idx = sl_row[k];
        const float4* wrow = reinterpret_cast<const float4*>(weight + (size_t)idx * D_DIM);

        // Issue all 4 independent LDG.128 up front (MLP), then FMA against smem embed.
        float4 w0 = wrow[lane +  0];
        float4 w1 = wrow[lane + 32];
        float4 w2 = wrow[lane + 64];
        float4 w3 = wrow[lane + 96];

        float4 e0 = s_embed[lane +  0];
        float4 e1 = s_embed[lane + 32];
        float4 e2 = s_embed[lane + 64];
        float4 e3 = s_embed[lane + 96];

        float sum = w0.x * e0.x + w0.y * e0.y + w0.z * e0.z + w0.w * e0.w;
        sum      += w1.x * e1.x + w1.y * e1.y + w1.z * e1.z + w1.w * e1.w;
        sum      += w2.x * e2.x + w2.y * e2.y + w2.z * e2.z + w2.w * e2.w;
        sum      += w3.x * e3.x + w3.y * e3.y + w3.z * e3.z + w3.w * e3.w;

        // Warp butterfly reduction
        #pragma unroll
        for (int off = 16; off > 0; off >>= 1)
            sum += __shfl_xor_sync(0xFFFFFFFFu, sum, off);

        if (lane == 0)
            out[(size_t)b * K_DIM + k] = sum + __ldg(bias + idx);
    }
}

extern "C" void kernel_launch(void* const* d_in, const int* in_sizes, int n_in,
                              void* d_out, int out_size)
{
    const float* embed     = (const float*)d_in[0];  // [B, D] f32
    const int*   shortlist = (const int*)d_in[1];    // [B, K] i32 (JAX x64-disabled downcast)
    const float* weight    = (const float*)d_in[2];  // [L, D] f32
    const float* bias      = (const float*)d_in[3];  // [L, 1] f32
    float*       out       = (float*)d_out;          // [B, K] f32

    dim3 grid(B_DIM, SPLITS);
    sparse_linear_kernel<<<grid, THREADS>>>(embed, shortlist, weight, bias, out);
}

// round 10
// speedup vs baseline: 1.2936x; 1.2936x over previous
#include <cuda_runtime.h>
#include <cuda_bf16.h>

// SparseLinear: out[b,k] = dot(embed[b,:], weight[shortlist[b,k],:]) + bias[shortlist[b,k]]
// B=256, K=500, D=512, L=262144  (shortlist buffer is int32: JAX x64 disabled)
//
// R9 post-mortem: 55.8us, DRAM 50.5%, 4.0 TB/s — latency-limited, not BW-limited.
// Per-warp serial chain (idx load -> 4 LDG -> FMA -> 5 dependent SHFL) leaves
// loads out of flight ~half the time. R10: prefetch all indices per warp up
// front + software-pipeline the row loads (issue row i+1's LDG.128s before
// reducing row i) so weight loads stay in flight ~100% of the time.

#define B_DIM 256
#define K_DIM 500
#define D_DIM 512
#define SPLITS 8
#define K_PER_BLOCK ((K_DIM + SPLITS - 1) / SPLITS)   // 63
#define THREADS 256
#define WARPS (THREADS / 32)                          // 8
#define MAX_ITERS ((K_PER_BLOCK + WARPS - 1) / WARPS) // 8

__global__ __launch_bounds__(THREADS)
void sparse_linear_kernel(const float* __restrict__ embed,
                          const int* __restrict__ shortlist,
                          const float* __restrict__ weight,
                          const float* __restrict__ bias,
                          float* __restrict__ out)
{
    __shared__ float4 s_embed[D_DIM / 4];   // 128 float4 = 2KB

    const int b    = blockIdx.x;
    const int tid  = threadIdx.x;
    const int warp = tid >> 5;
    const int lane = tid & 31;

    // Cooperative load of embed[b] into smem (threads 0..127, one float4 each)
    const float4* embed_row = reinterpret_cast<const float4*>(embed + (size_t)b * D_DIM);
    if (tid < D_DIM / 4) {
        s_embed[tid] = embed_row[tid];
    }
    __syncthreads();

    const int k_begin = blockIdx.y * K_PER_BLOCK;
    int k_end = k_begin + K_PER_BLOCK;
    if (k_end > K_DIM) k_end = K_DIM;

    const int* sl_row = shortlist + (size_t)b * K_DIM;
    const int k0 = k_begin + warp;   // this warp's first k; stride = WARPS

    // ---- Phase 0: prefetch ALL indices for this warp (independent broadcast LDGs)
    int idxs[MAX_ITERS];
    #pragma unroll
    for (int i = 0; i < MAX_ITERS; i++) {
        const int k = k0 + i * WARPS;
        idxs[i] = (k < k_end) ? __ldg(sl_row + k) : 0;
    }

    if (k0 >= k_end) return;

    // Keep embed slice for this lane in registers (loop-invariant)
    const float4 e0 = s_embed[lane +  0];
    const float4 e1 = s_embed[lane + 32];
    const float4 e2 = s_embed[lane + 64];
    const float4 e3 = s_embed[lane + 96];

    // ---- Phase 1: preload row 0 (+ its bias)
    float4 w0, w1, w2, w3;
    float  bv;
    {
        const float4* wrow = reinterpret_cast<const float4*>(weight + (size_t)idxs[0] * D_DIM);
        w0 = wrow[lane +  0];
        w1 = wrow[lane + 32];
        w2 = wrow[lane + 64];
        w3 = wrow[lane + 96];
        bv = __ldg(bias + idxs[0]);
    }

    // ---- Phase 2: pipelined main loop — prefetch row i+1, compute row i
    #pragma unroll
    for (int i = 0; i < MAX_ITERS; i++) {
        const int k = k0 + i * WARPS;
        if (k >= k_end) break;

        const bool has_next = (k + WARPS < k_end) && (i + 1 < MAX_ITERS);

        // Prefetch next row + bias while current row's data is consumed below.
        float4 n0, n1, n2, n3;
        float  nbv = 0.0f;
        if (has_next) {
            const float4* nrow =
                reinterpret_cast<const float4*>(weight + (size_t)idxs[i + 1] * D_DIM);
            n0 = nrow[lane +  0];
            n1 = nrow[lane + 32];
            n2 = nrow[lane + 64];
            n3 = nrow[lane + 96];
            nbv = __ldg(bias + idxs[i + 1]);
        }

        // Compute current row's partial dot
        float sum = w0.x * e0.x + w0.y * e0.y + w0.z * e0.z + w0.w * e0.w;
        sum      += w1.x * e1.x + w1.y * e1.y + w1.z * e1.z + w1.w * e1.w;
        sum      += w2.x * e2.x + w2.y * e2.y + w2.z * e2.z + w2.w * e2.w;
        sum      += w3.x * e3.x + w3.y * e3.y + w3.z * e3.z + w3.w * e3.w;

        // Warp butterfly reduction (overlaps with the prefetch loads in flight)
        #pragma unroll
        for (int off = 16; off > 0; off >>= 1)
            sum += __shfl_xor_sync(0xFFFFFFFFu, sum, off);

        if (lane == 0)
            out[(size_t)b * K_DIM + k] = sum + bv;

        // Rotate pipeline registers
        w0 = n0; w1 = n1; w2 = n2; w3 = n3; bv = nbv;
    }
}

extern "C" void kernel_launch(void* const* d_in, const int* in_sizes, int n_in,
                              void* d_out, int out_size)
{
    const float* embed     = (const float*)d_in[0];  // [B, D] f32
    const int*   shortlist = (const int*)d_in[1];    // [B, K] i32
    const float* weight    = (const float*)d_in[2];  // [L, D] f32
    const float* bias      = (const float*)d_in[3];  // [L, 1] f32
    float*       out       = (float*)d_out;          // [B, K] f32

    dim3 grid(B_DIM, SPLITS);
    sparse_linear_kernel<<<grid, THREADS>>>(embed, shortlist, weight, bias, out);
}